// round 17
// baseline (speedup 1.0000x reference)
#include <cuda_runtime.h>
#include <cuda_bf16.h>
#include <math.h>
#include <stdint.h>

#define N_NODES 100000
#define N_EDGES 3200000
#define IN_CH   602
#define HID     16
#define OUT_CH  41

#define SCAN_BLK 1024
#define NB_SCAN  ((N_NODES + SCAN_BLK - 1) / SCAN_BLK)   // 98

// ---- mma gemm config ----
#define GM_ROWS   64                        // rows per block (4 warps x m16)
#define GM_KC     64                        // K per staged chunk
#define GM_NCH    10                        // ceil(602/64)
#define GM_GRID   ((N_NODES + GM_ROWS - 1) / GM_ROWS)    // 1563
#define A_STR_W   36                        // smem row stride in 32-bit words (72 bf16)

// Scratch (device globals; no allocation allowed)
__device__ float g_h1   [N_NODES * HID];
__device__ float g_r    [N_NODES * HID];
__device__ int   g_deg  [N_NODES];
__device__ int   g_excl [N_NODES];
__device__ int   g_blksum[128];
__device__ int   g_rowptr[N_NODES + 1];
__device__ int   g_cursor[N_NODES];
__device__ int   g_csr  [N_EDGES];

__device__ __forceinline__ uint32_t smem_u32(const void* p) {
    uint32_t a;
    asm("{ .reg .u64 t; cvta.to.shared.u64 t, %1; cvt.u32.u64 %0, t; }" : "=r"(a) : "l"(p));
    return a;
}

__device__ __forceinline__ void ldmat4(uint32_t& r0, uint32_t& r1,
                                       uint32_t& r2, uint32_t& r3, uint32_t addr) {
    asm volatile("ldmatrix.sync.aligned.m8n8.x4.shared.b16 {%0,%1,%2,%3}, [%4];"
                 : "=r"(r0), "=r"(r1), "=r"(r2), "=r"(r3) : "r"(addr));
}

__device__ __forceinline__ void mma16816(float4& d,
                                         uint32_t a0, uint32_t a1, uint32_t a2, uint32_t a3,
                                         uint32_t b0, uint32_t b1) {
    asm volatile("mma.sync.aligned.m16n8k16.row.col.f32.bf16.bf16.f32 "
                 "{%0,%1,%2,%3}, {%4,%5,%6,%7}, {%8,%9}, {%0,%1,%2,%3};"
                 : "+f"(d.x), "+f"(d.y), "+f"(d.z), "+f"(d.w)
                 : "r"(a0), "r"(a1), "r"(a2), "r"(a3), "r"(b0), "r"(b1));
}

// split float pair -> packed bf16 hi pair + residuals
__device__ __forceinline__ uint32_t split_hi(float a, float b, float& ra, float& rb) {
    __nv_bfloat16 ha = __float2bfloat16_rn(a);
    __nv_bfloat16 hb = __float2bfloat16_rn(b);
    ra = a - __bfloat162float(ha);
    rb = b - __bfloat162float(hb);
    __nv_bfloat162 p = __halves2bfloat162(ha, hb);
    return *(uint32_t*)&p;
}
__device__ __forceinline__ uint32_t pack_bf2(float a, float b) {
    __nv_bfloat162 p = __halves2bfloat162(__float2bfloat16_rn(a), __float2bfloat16_rn(b));
    return *(uint32_t*)&p;
}

// ---------------------------------------------------------------------------
// K1: h1[N,16] = x[N,602] @ W1[602,16] on HMMA tensor cores (mma.sync bf16,
// hi/lo split, fp32 accum).  64 rows/block, K chunks of 64, double-buffered
// register prefetch of x; A-frags via ldmatrix, B-frags via direct LDG (L1).
// ---------------------------------------------------------------------------
__global__ __launch_bounds__(128)
void gemm1_kernel(const float* __restrict__ x,
                  const float* __restrict__ W1,
                  float* __restrict__ h1) {
    __shared__ uint32_t aHi[GM_ROWS][A_STR_W];
    __shared__ uint32_t aLo[GM_ROWS][A_STR_W];

    const int tid  = threadIdx.x;
    const int warp = tid >> 5;
    const int lane = tid & 31;
    const int row_base = blockIdx.x * GM_ROWS;

    // staging mapping: thread -> (row sr, k-half kh); 16 float2 per thread
    const int sr = tid >> 1;
    const int kh = tid & 1;
    int grow_s = row_base + sr;
    int crs = (grow_s < N_NODES) ? grow_s : 0;
    const float* xrow = x + (size_t)crs * IN_CH;

    const uint32_t aHi_base = smem_u32(aHi);
    const uint32_t aLo_base = smem_u32(aLo);

    float2 px[16];
    float4 acc[2];
    acc[0] = make_float4(0.f, 0.f, 0.f, 0.f);
    acc[1] = make_float4(0.f, 0.f, 0.f, 0.f);

    // prefetch chunk 0
    #pragma unroll
    for (int i = 0; i < 16; i++) {
        int gk = kh * 32 + 2 * i;
        px[i] = (gk < IN_CH) ? *(const float2*)(xrow + gk) : make_float2(0.f, 0.f);
    }

    // ldmatrix lane geometry
    const int mat = lane >> 3;
    const int mr  = lane & 7;
    const int arow = warp * 16 + (mat & 1) * 8 + mr;

    #pragma unroll 1
    for (int c = 0; c < GM_NCH; c++) {
        // store staged chunk as bf16 hi/lo
        #pragma unroll
        for (int i = 0; i < 16; i++) {
            float ra, rb;
            uint32_t hp = split_hi(px[i].x, px[i].y, ra, rb);
            uint32_t lp = pack_bf2(ra, rb);
            int w = kh * 16 + i;            // word index = k/2
            aHi[sr][w] = hp;
            aLo[sr][w] = lp;
        }
        __syncthreads();

        // prefetch next chunk (overlaps mma below)
        if (c + 1 < GM_NCH) {
            int kb = (c + 1) * GM_KC;
            #pragma unroll
            for (int i = 0; i < 16; i++) {
                int gk = kb + kh * 32 + 2 * i;
                px[i] = (gk < IN_CH) ? *(const float2*)(xrow + gk) : make_float2(0.f, 0.f);
            }
        }

        // 4 k16 steps
        #pragma unroll
        for (int s = 0; s < 4; s++) {
            int acolw = s * 8 + (mat >> 1) * 4;     // word index within row
            uint32_t offw = (uint32_t)(arow * A_STR_W + acolw) * 4u;
            uint32_t ah0, ah1, ah2, ah3, al0, al1, al2, al3;
            ldmat4(ah0, ah1, ah2, ah3, aHi_base + offw);
            ldmat4(al0, al1, al2, al3, aLo_base + offw);

            int k0 = c * GM_KC + s * 16 + (lane & 3) * 2;
            #pragma unroll
            for (int hf = 0; hf < 2; hf++) {
                int nn = hf * 8 + (lane >> 2);
                float w00 = (k0     < IN_CH) ? W1[(size_t)(k0    ) * HID + nn] : 0.f;
                float w01 = (k0 + 1 < IN_CH) ? W1[(size_t)(k0 + 1) * HID + nn] : 0.f;
                float w08 = (k0 + 8 < IN_CH) ? W1[(size_t)(k0 + 8) * HID + nn] : 0.f;
                float w09 = (k0 + 9 < IN_CH) ? W1[(size_t)(k0 + 9) * HID + nn] : 0.f;
                float r0, r1, r8, r9;
                uint32_t bh0 = split_hi(w00, w01, r0, r1);
                uint32_t bh1 = split_hi(w08, w09, r8, r9);
                uint32_t bl0 = pack_bf2(r0, r1);
                uint32_t bl1 = pack_bf2(r8, r9);
                mma16816(acc[hf], ah0, ah1, ah2, ah3, bh0, bh1);   // hi*hi
                mma16816(acc[hf], ah0, ah1, ah2, ah3, bl0, bl1);   // hi*lo
                mma16816(acc[hf], al0, al1, al2, al3, bh0, bh1);   // lo*hi
            }
        }
        __syncthreads();
    }

    // epilogue: c-frag -> h1
    int r0 = row_base + warp * 16 + (lane >> 2);
    int n0 = (lane & 3) * 2;
    #pragma unroll
    for (int hf = 0; hf < 2; hf++) {
        if (r0 < N_NODES)
            *(float2*)(h1 + (size_t)r0 * 16 + hf * 8 + n0) = make_float2(acc[hf].x, acc[hf].y);
        if (r0 + 8 < N_NODES)
            *(float2*)(h1 + (size_t)(r0 + 8) * 16 + hf * 8 + n0) = make_float2(acc[hf].z, acc[hf].w);
    }
}

// ---------------------------------------------------------------------------
// CSR construction  (proven path)
// ---------------------------------------------------------------------------
__global__ void deg_kernel(const int* __restrict__ dst, int* __restrict__ deg) {
    int e = blockIdx.x * blockDim.x + threadIdx.x;
    if (e < N_EDGES) atomicAdd(&deg[dst[e]], 1);
}

__global__ __launch_bounds__(SCAN_BLK)
void scan1_kernel(const int* __restrict__ deg,
                  int* __restrict__ excl,
                  int* __restrict__ blksum) {
    __shared__ int wsum[32];
    int tid = threadIdx.x, lane = tid & 31, wid = tid >> 5;
    int i = blockIdx.x * SCAN_BLK + tid;
    int v = (i < N_NODES) ? deg[i] : 0;
    int x = v;
    #pragma unroll
    for (int d = 1; d < 32; d <<= 1) {
        int t = __shfl_up_sync(0xffffffffu, x, d);
        if (lane >= d) x += t;
    }
    if (lane == 31) wsum[wid] = x;
    __syncthreads();
    if (wid == 0) {
        int s = wsum[lane];
        #pragma unroll
        for (int d = 1; d < 32; d <<= 1) {
            int t = __shfl_up_sync(0xffffffffu, s, d);
            if (lane >= d) s += t;
        }
        wsum[lane] = s;
    }
    __syncthreads();
    int woff = (wid == 0) ? 0 : wsum[wid - 1];
    if (i < N_NODES) excl[i] = woff + x - v;
    if (tid == SCAN_BLK - 1) blksum[blockIdx.x] = wsum[31];
}

__global__ __launch_bounds__(128)
void scan2_kernel(int* __restrict__ blksum) {
    __shared__ int ws[4];
    int tid = threadIdx.x, lane = tid & 31, wid = tid >> 5;
    int v = (tid < NB_SCAN) ? blksum[tid] : 0;
    int x = v;
    #pragma unroll
    for (int d = 1; d < 32; d <<= 1) {
        int t = __shfl_up_sync(0xffffffffu, x, d);
        if (lane >= d) x += t;
    }
    if (lane == 31) ws[wid] = x;
    __syncthreads();
    int woff = 0;
    #pragma unroll
    for (int w = 0; w < 4; w++) if (w < wid) woff += ws[w];
    if (tid < NB_SCAN) blksum[tid] = woff + x - v;
}

__global__ void scan3_kernel(const int* __restrict__ excl,
                             const int* __restrict__ blksum,
                             int* __restrict__ rowptr,
                             int* __restrict__ cursor) {
    int i = blockIdx.x * blockDim.x + threadIdx.x;
    if (i >= N_NODES) return;
    int v = excl[i] + blksum[i / SCAN_BLK];
    rowptr[i] = v;
    cursor[i] = v;
    if (i == 0) rowptr[N_NODES] = N_EDGES;
}

__global__ void fill_kernel(const int* __restrict__ src,
                            const int* __restrict__ dst,
                            int* __restrict__ cursor,
                            int* __restrict__ csr_src) {
    int e = blockIdx.x * blockDim.x + threadIdx.x;
    if (e >= N_EDGES) return;
    int slot = atomicAdd(&cursor[dst[e]], 1);
    csr_src[slot] = src[e];
}

// ---------------------------------------------------------------------------
// Shared gather body (proven round-16): tiered edge loop, group-masked shfl.
// ---------------------------------------------------------------------------
__device__ __forceinline__ float4 gather_mean(const float4* __restrict__ hv,
                                              const int* __restrict__ csr_src,
                                              int beg, int end, int c4,
                                              unsigned gmask) {
    float4 s = make_float4(0.f, 0.f, 0.f, 0.f);
    int j = beg;
    if ((j & 1) && j < end) {
        float4 v = hv[(size_t)csr_src[j] * 4 + c4];
        s.x += v.x; s.y += v.y; s.z += v.z; s.w += v.w;
        j++;
    }
    for (; j + 8 <= end; j += 8) {
        int2 myi = *(const int2*)(csr_src + j + 2 * c4);
        #pragma unroll
        for (int q = 0; q < 4; q++) {
            int ia = __shfl_sync(gmask, myi.x, q, 4);
            int ib = __shfl_sync(gmask, myi.y, q, 4);
            float4 va = hv[(size_t)ia * 4 + c4];
            float4 vb = hv[(size_t)ib * 4 + c4];
            s.x += va.x + vb.x;
            s.y += va.y + vb.y;
            s.z += va.z + vb.z;
            s.w += va.w + vb.w;
        }
    }
    if (j + 4 <= end) {
        int myi = csr_src[j + c4];
        int s0 = __shfl_sync(gmask, myi, 0, 4);
        int s1 = __shfl_sync(gmask, myi, 1, 4);
        int s2 = __shfl_sync(gmask, myi, 2, 4);
        int s3 = __shfl_sync(gmask, myi, 3, 4);
        float4 v0 = hv[(size_t)s0 * 4 + c4];
        float4 v1 = hv[(size_t)s1 * 4 + c4];
        float4 v2 = hv[(size_t)s2 * 4 + c4];
        float4 v3 = hv[(size_t)s3 * 4 + c4];
        s.x += (v0.x + v1.x) + (v2.x + v3.x);
        s.y += (v0.y + v1.y) + (v2.y + v3.y);
        s.z += (v0.z + v1.z) + (v2.z + v3.z);
        s.w += (v0.w + v1.w) + (v2.w + v3.w);
        j += 4;
    }
    for (; j < end; j++) {
        float4 v = hv[(size_t)csr_src[j] * 4 + c4];
        s.x += v.x; s.y += v.y; s.z += v.z; s.w += v.w;
    }
    float inv = 1.f / fmaxf((float)(end - beg), 1.f);
    return make_float4(s.x * inv, s.y * inv, s.z * inv, s.w * inv);
}

__global__ void gather1_kernel(const float* __restrict__ h,
                               const int* __restrict__ rowptr,
                               const int* __restrict__ csr_src,
                               const float* __restrict__ bias,
                               float* __restrict__ out) {
    int t = blockIdx.x * blockDim.x + threadIdx.x;
    int nid = t >> 2;
    int c4  = t & 3;
    unsigned gmask = 0xFu << ((threadIdx.x & 31) & ~3);
    if (nid >= N_NODES) return;
    int beg = rowptr[nid];
    int end = rowptr[nid + 1];
    float4 m = gather_mean((const float4*)h, csr_src, beg, end, c4, gmask);
    float4 bb = __ldg(((const float4*)bias) + c4);
    m.x = fmaxf(m.x + bb.x, 0.f);
    m.y = fmaxf(m.y + bb.y, 0.f);
    m.z = fmaxf(m.z + bb.z, 0.f);
    m.w = fmaxf(m.w + bb.w, 0.f);
    ((float4*)out)[(size_t)nid * 4 + c4] = m;
}

__global__ void gather2_out_kernel(const float* __restrict__ h,
                                   const int* __restrict__ rowptr,
                                   const int* __restrict__ csr_src,
                                   const float* __restrict__ W2,
                                   const float* __restrict__ b2,
                                   float* __restrict__ out) {
    __shared__ float w2s[HID * OUT_CH];
    __shared__ float b2s[OUT_CH];
    for (int i = threadIdx.x; i < HID * OUT_CH; i += blockDim.x) w2s[i] = W2[i];
    for (int i = threadIdx.x; i < OUT_CH;       i += blockDim.x) b2s[i] = b2[i];
    __syncthreads();

    int t = blockIdx.x * blockDim.x + threadIdx.x;
    int nid = t >> 2;
    int c4  = t & 3;
    unsigned gmask = 0xFu << ((threadIdx.x & 31) & ~3);
    if (nid >= N_NODES) return;
    int beg = rowptr[nid];
    int end = rowptr[nid + 1];
    float4 m = gather_mean((const float4*)h, csr_src, beg, end, c4, gmask);

    float ma[16];
    #pragma unroll
    for (int sl = 0; sl < 4; sl++) {
        ma[sl * 4 + 0] = __shfl_sync(gmask, m.x, sl, 4);
        ma[sl * 4 + 1] = __shfl_sync(gmask, m.y, sl, 4);
        ma[sl * 4 + 2] = __shfl_sync(gmask, m.z, sl, 4);
        ma[sl * 4 + 3] = __shfl_sync(gmask, m.w, sl, 4);
    }

    float o[11];
    float lmax = -1e30f;
    int cnt = 0;
    for (int jj = c4; jj < OUT_CH; jj += 4, cnt++) {
        float v = b2s[jj];
        #pragma unroll
        for (int k = 0; k < HID; k++)
            v += ma[k] * w2s[k * OUT_CH + jj];
        o[cnt] = v;
        lmax = fmaxf(lmax, v);
    }
    lmax = fmaxf(lmax, __shfl_xor_sync(gmask, lmax, 1));
    lmax = fmaxf(lmax, __shfl_xor_sync(gmask, lmax, 2));
    float lsum = 0.f;
    for (int i = 0; i < cnt; i++) lsum += __expf(o[i] - lmax);
    lsum += __shfl_xor_sync(gmask, lsum, 1);
    lsum += __shfl_xor_sync(gmask, lsum, 2);
    float ls = __logf(lsum) + lmax;

    float* op = out + (size_t)nid * OUT_CH;
    int i = 0;
    for (int jj = c4; jj < OUT_CH; jj += 4, i++) op[jj] = o[i] - ls;
}

// ---------------------------------------------------------------------------
extern "C" void kernel_launch(void* const* d_in, const int* in_sizes, int n_in,
                              void* d_out, int out_size) {
    const float* x  = (const float*)d_in[0];
    const int*   ei = (const int*)  d_in[1];
    const float* W1 = (const float*)d_in[2];
    const float* b1 = (const float*)d_in[3];
    const float* W2 = (const float*)d_in[4];
    const float* b2 = (const float*)d_in[5];
    float* out = (float*)d_out;

    const int* src = ei;
    const int* dst = ei + N_EDGES;

    float *p_h1, *p_r;
    int *p_deg, *p_excl, *p_blksum, *p_rowptr, *p_cursor, *p_csr;
    cudaGetSymbolAddress((void**)&p_h1,     g_h1);
    cudaGetSymbolAddress((void**)&p_r,      g_r);
    cudaGetSymbolAddress((void**)&p_deg,    g_deg);
    cudaGetSymbolAddress((void**)&p_excl,   g_excl);
    cudaGetSymbolAddress((void**)&p_blksum, g_blksum);
    cudaGetSymbolAddress((void**)&p_rowptr, g_rowptr);
    cudaGetSymbolAddress((void**)&p_cursor, g_cursor);
    cudaGetSymbolAddress((void**)&p_csr,    g_csr);

    // Side stream + fork/join events (created on first call, which is the
    // uncaptured correctness run; reused identically during graph capture).
    static cudaStream_t s_csr = nullptr;
    static cudaEvent_t  ev_fork = nullptr, ev_join = nullptr;
    if (s_csr == nullptr) {
        cudaStreamCreateWithFlags(&s_csr, cudaStreamNonBlocking);
        cudaEventCreateWithFlags(&ev_fork, cudaEventDisableTiming);
        cudaEventCreateWithFlags(&ev_join, cudaEventDisableTiming);
    }

    // Fork: CSR chain on side stream, gemm on main stream — independent.
    cudaEventRecord(ev_fork, 0);
    cudaStreamWaitEvent(s_csr, ev_fork, 0);

    cudaMemsetAsync(p_deg, 0, sizeof(int) * N_NODES, s_csr);
    deg_kernel <<<(N_EDGES + 255) / 256, 256, 0, s_csr>>>(dst, p_deg);
    scan1_kernel<<<NB_SCAN, SCAN_BLK, 0, s_csr>>>(p_deg, p_excl, p_blksum);
    scan2_kernel<<<1, 128, 0, s_csr>>>(p_blksum);
    scan3_kernel<<<(N_NODES + 255) / 256, 256, 0, s_csr>>>(p_excl, p_blksum, p_rowptr, p_cursor);
    fill_kernel <<<(N_EDGES + 255) / 256, 256, 0, s_csr>>>(src, dst, p_cursor, p_csr);
    cudaEventRecord(ev_join, s_csr);

    // K1 on main stream (HMMA tensor cores), overlapped with CSR build
    gemm1_kernel<<<GM_GRID, 128>>>(x, W1, p_h1);

    // Join: gather1 needs both h1 and the CSR
    cudaStreamWaitEvent(0, ev_join, 0);

    gather1_kernel<<<(N_NODES * 4 + 255) / 256, 256>>>(p_h1, p_rowptr, p_csr, b1, p_r);
    gather2_out_kernel<<<(N_NODES * 4 + 255) / 256, 256>>>(p_r, p_rowptr, p_csr, W2, b2, out);
}